// round 16
// baseline (speedup 1.0000x reference)
#include <cuda_runtime.h>
#include <cuda_bf16.h>
#include <cuda_fp16.h>
#include <math_constants.h>
#include <cstdint>

#define N_NODES 50000
#define N_EDGES 800000
#define D_IN 128
#define D_H 128
#define D_OUT 32

// ---------------- scratch (device globals; no allocation allowed) ----------------
__device__ int    g_cnt[N_NODES];          // zero-initialized at module load; scan re-zeroes
__device__ int    g_row_ptr[N_NODES + 1];
__device__ int    g_rank[N_EDGES];
__device__ int    g_col[N_EDGES];
__device__ float  g_agg[(size_t)N_NODES * D_H];    // fp32 agg (layer 2)
__device__ __half g_agg16[(size_t)N_NODES * D_H];  // fp16 agg (layer 1)
__device__ float  g_h[(size_t)N_NODES * D_H];
__device__ __half g_x16[(size_t)N_NODES * D_H];
__device__ __half g_h16[(size_t)N_NODES * D_H];
__device__ __half g_B1h[128 * 256];   // layer-1 weights [N=128][K=256] K-major, fp16
__device__ float  g_B2t[32 * 256];    // layer-2 weights [N=32][K=256]  K-major, tf32-rounded
__device__ float  g_colsum[D_H];
__device__ float  g_colsumsq[D_H];

__device__ __forceinline__ float f2tf32(float x) {
    float r;
    asm("cvt.rna.tf32.f32 %0, %1;" : "=f"(r) : "f"(x));
    return r;
}

// ---------------- CSR build + all setup in one kernel ----------------
__global__ void hist_kernel(const int* __restrict__ dst, int E,
                            const float* __restrict__ x, int total4, int T,
                            const float* __restrict__ Wl1, const float* __restrict__ Wr1,
                            const float* __restrict__ Wl2, const float* __restrict__ Wr2) {
    int t = blockIdx.x * blockDim.x + threadIdx.x;
    int e0 = t * 2;
    if (e0 < E) {
        int d0 = __ldg(&dst[e0]);
        if (e0 + 1 < E) {
            int d1 = __ldg(&dst[e0 + 1]);
            g_rank[e0] = atomicAdd(&g_cnt[d0], 1);
            g_rank[e0 + 1] = atomicAdd(&g_cnt[d1], 1);
        } else {
            g_rank[e0] = atomicAdd(&g_cnt[d0], 1);
        }
    }
    if (t < 128 * 256) {
        int n = t >> 8, k = t & 255;
        float v = (k < 128) ? __ldg(&Wl1[n * 128 + k]) : __ldg(&Wr1[n * 128 + (k - 128)]);
        g_B1h[t] = __float2half_rn(v);
    }
    if (t < 32 * 256) {
        int n = t >> 8, k = t & 255;
        float v = (k < 128) ? __ldg(&Wl2[n * 128 + k]) : __ldg(&Wr2[n * 128 + (k - 128)]);
        g_B2t[t] = f2tf32(v);
    }
    if (t < 128) { g_colsum[t] = 0.f; g_colsumsq[t] = 0.f; }
    const float4* X4 = reinterpret_cast<const float4*>(x);
    for (int idx = t; idx < total4; idx += T) {
        float4 v = __ldg(&X4[idx]);
        __half2 a = __floats2half2_rn(v.x, v.y);
        __half2 b = __floats2half2_rn(v.z, v.w);
        uint2 o;
        o.x = *reinterpret_cast<uint32_t*>(&a);
        o.y = *reinterpret_cast<uint32_t*>(&b);
        *reinterpret_cast<uint2*>(&g_x16[(size_t)idx * 4]) = o;
    }
}

// ---------------- triangular parallel exclusive scan (coalesced, multi-block) ----------
__global__ __launch_bounds__(256)
void scan_kernel(int n) {
    __shared__ int red[256];
    int tid = threadIdx.x;
    int base = blockIdx.x * 256;

    int sum = 0;
    for (int i = tid; i < base; i += 256) sum += g_cnt[i];
    red[tid] = sum;
    __syncthreads();
    #pragma unroll
    for (int d = 128; d > 0; d >>= 1) {
        if (tid < d) red[tid] += red[tid + d];
        __syncthreads();
    }
    int blockOff = red[0];
    __syncthreads();

    int i = base + tid;
    int v = (i < n) ? g_cnt[i] : 0;
    red[tid] = v;
    __syncthreads();
    #pragma unroll
    for (int d = 1; d < 256; d <<= 1) {
        int u = (tid >= d) ? red[tid - d] : 0;
        __syncthreads();
        red[tid] += u;
        __syncthreads();
    }
    int incl = red[tid];
    if (i < n) {
        g_row_ptr[i] = blockOff + incl - v;  // exclusive prefix
        g_cnt[i] = 0;                        // restore invariant for next call
        if (i == n - 1) g_row_ptr[n] = blockOff + incl;
    }
}

// atomic-free scatter, 2 edges/thread
__global__ void scatter_kernel(const int* __restrict__ src, const int* __restrict__ dst, int E) {
    int t = blockIdx.x * blockDim.x + threadIdx.x;
    int e0 = t * 2;
    if (e0 + 1 < E) {
        int d0 = __ldg(&dst[e0]),      d1 = __ldg(&dst[e0 + 1]);
        int r0 = __ldg(&g_rank[e0]),   r1 = __ldg(&g_rank[e0 + 1]);
        int s0 = __ldg(&src[e0]),      s1 = __ldg(&src[e0 + 1]);
        int p0 = __ldg(&g_row_ptr[d0]), p1 = __ldg(&g_row_ptr[d1]);
        g_col[p0 + r0] = s0;
        g_col[p1 + r1] = s1;
    } else if (e0 < E) {
        int d0 = __ldg(&dst[e0]);
        g_col[__ldg(&g_row_ptr[d0]) + __ldg(&g_rank[e0])] = __ldg(&src[e0]);
    }
}

// ---------------- scatter-max aggregation: 2 warps per node (feature-halves) ----------------
// Work unit = (node, half). Each lane loads one half2 (4B); 32 lanes cover 64 features.
// Doubles independent edge-walk chains vs warp-per-node -> better latency hiding.
// XFORM=false: out = fp16 max (exact), to AGGH.
// XFORM=true:  track max AND min; apply relu(fma(sel, sc, sh)) once per node
//              (monotone affine+relu commutes with max; sc<0 selects min). Out fp32 tf32.
template <bool XFORM>
__global__ void agg16h_kernel(const __half* __restrict__ X16,
                              float* __restrict__ AGGF, __half* __restrict__ AGGH, int nNodes,
                              const float* __restrict__ gamma, const float* __restrict__ beta,
                              float invM) {
    __shared__ float s_sc[XFORM ? 128 : 1];
    __shared__ float s_sh[XFORM ? 128 : 1];
    int tid = threadIdx.x;
    if (XFORM) {
        if (tid < 128) {
            float mean = g_colsum[tid] * invM;
            float var = g_colsumsq[tid] * invM - mean * mean;
            float sc = gamma[tid] * rsqrtf(var + 1e-5f);
            s_sc[tid] = sc;
            s_sh[tid] = beta[tid] - mean * sc;
        }
        __syncthreads();
    }
    int unit = (blockIdx.x * blockDim.x + tid) >> 5;
    int lane = tid & 31;
    int node = unit >> 1;
    int half = unit & 1;
    if (node >= nNodes) return;
    int s = g_row_ptr[node];
    int e = g_row_ptr[node + 1];
    // feature offset in uint (half2) units: row = 64 uints; this warp covers 32 of them
    uint32_t foff = (uint32_t)half * 32u + (uint32_t)lane;
    const uint32_t* X1 = reinterpret_cast<const uint32_t*>(X16);

    const uint32_t NEGI = 0xFC00FC00u;  // (-inf, -inf)
    const uint32_t POSI = 0x7C007C00u;  // (+inf, +inf)
    __half2 mx = *reinterpret_cast<const __half2*>(&NEGI);
    __half2 mn = *reinterpret_cast<const __half2*>(&POSI);

    int i = s;
    while (i < e && (i & 3)) {
        uint32_t c = (uint32_t)__ldg(&g_col[i]);
        uint32_t p = __ldg(&X1[c * 64u + foff]);
        __half2 a = *reinterpret_cast<const __half2*>(&p);
        mx = __hmax2(mx, a);
        if (XFORM) mn = __hmin2(mn, a);
        i++;
    }
    #pragma unroll 2
    for (; i + 4 <= e; i += 4) {
        int4 c = *reinterpret_cast<const int4*>(&g_col[i]);  // one 16B uniform load
        uint32_t p0 = __ldg(&X1[(uint32_t)c.x * 64u + foff]);
        uint32_t p1 = __ldg(&X1[(uint32_t)c.y * 64u + foff]);
        uint32_t p2 = __ldg(&X1[(uint32_t)c.z * 64u + foff]);
        uint32_t p3 = __ldg(&X1[(uint32_t)c.w * 64u + foff]);
        __half2 a = *reinterpret_cast<const __half2*>(&p0);
        __half2 b = *reinterpret_cast<const __half2*>(&p1);
        __half2 d = *reinterpret_cast<const __half2*>(&p2);
        __half2 f = *reinterpret_cast<const __half2*>(&p3);
        mx = __hmax2(mx, __hmax2(__hmax2(a, b), __hmax2(d, f)));
        if (XFORM) mn = __hmin2(mn, __hmin2(__hmin2(a, b), __hmin2(d, f)));
    }
    for (; i < e; i++) {
        uint32_t c = (uint32_t)__ldg(&g_col[i]);
        uint32_t p = __ldg(&X1[c * 64u + foff]);
        __half2 a = *reinterpret_cast<const __half2*>(&p);
        mx = __hmax2(mx, a);
        if (XFORM) mn = __hmin2(mn, a);
    }

    if (!XFORM) {
        uint32_t o = (s == e) ? 0u : *reinterpret_cast<uint32_t*>(&mx);
        reinterpret_cast<uint32_t*>(AGGH)[(size_t)node * 64 + foff] = o;
    } else {
        int fbase = (int)foff * 2;  // feature index of the low half
        float2 sc = *reinterpret_cast<const float2*>(&s_sc[fbase]);
        float2 sh = *reinterpret_cast<const float2*>(&s_sh[fbase]);
        float2 fx = __half22float2(mx);
        float2 fn = __half22float2(mn);
        float2 r;
        r.x = fmaxf(fmaf(sc.x >= 0.f ? fx.x : fn.x, sc.x, sh.x), 0.f);
        r.y = fmaxf(fmaf(sc.y >= 0.f ? fx.y : fn.y, sc.y, sh.y), 0.f);
        if (s == e) { r.x = 0.f; r.y = 0.f; }
        r.x = f2tf32(r.x); r.y = f2tf32(r.y);
        *reinterpret_cast<float2*>(&AGGF[(size_t)node * 128 + fbase]) = r;
    }
}

// ---------------- mma helpers ----------------
__device__ __forceinline__ void mma_f16(float* d, const uint32_t* a, const uint32_t* b) {
    asm volatile(
        "mma.sync.aligned.m16n8k16.row.col.f32.f16.f16.f32 "
        "{%0,%1,%2,%3}, {%4,%5,%6,%7}, {%8,%9}, {%0,%1,%2,%3};"
        : "+f"(d[0]), "+f"(d[1]), "+f"(d[2]), "+f"(d[3])
        : "r"(a[0]), "r"(a[1]), "r"(a[2]), "r"(a[3]), "r"(b[0]), "r"(b[1]));
}
__device__ __forceinline__ void mma_tf32(float* d, const uint32_t* a, const uint32_t* b) {
    asm volatile(
        "mma.sync.aligned.m16n8k8.row.col.f32.tf32.tf32.f32 "
        "{%0,%1,%2,%3}, {%4,%5,%6,%7}, {%8,%9}, {%0,%1,%2,%3};"
        : "+f"(d[0]), "+f"(d[1]), "+f"(d[2]), "+f"(d[3])
        : "r"(a[0]), "r"(a[1]), "r"(a[2]), "r"(a[3]), "r"(b[0]), "r"(b[1]));
}

// ---------------- layer-1 GEMM via mma.sync fp16 m16n8k16 (frozen) ----------------
#define G1H_STRIDE 132
#define G1H_SMEM_BYTES ((2 * 128 * G1H_STRIDE) * 4 + 256 * 4)

__global__ __launch_bounds__(256, 1)
void gemm1_f16_kernel(const __half* __restrict__ A0h, const __half* __restrict__ A1h,
                      const __half* __restrict__ Bh, const float* __restrict__ bias,
                      float* __restrict__ C, int M) {
    extern __shared__ uint32_t smh[];
    uint32_t* Bs = smh;                                  // [128][132] half2 units
    uint32_t* As = smh + 128 * G1H_STRIDE;               // [128][132]
    float* ssum = reinterpret_cast<float*>(smh + 2 * 128 * G1H_STRIDE);
    float* ssq  = ssum + 128;

    int tid = threadIdx.x;
    int lane = tid & 31;
    int wid = tid >> 5;
    int warpM = wid & 3;
    int warpN = wid >> 2;
    int g = lane >> 2;
    int tig = lane & 3;
    int m0 = blockIdx.x * 128;

    if (tid < 128) { ssum[tid] = 0.f; ssq[tid] = 0.f; }

    const uint4* B4 = reinterpret_cast<const uint4*>(Bh);
    #pragma unroll
    for (int j = 0; j < 16; j++) {
        int i = tid + 256 * j;
        int n = i >> 5, q = i & 31;
        uint4 v = __ldg(&B4[n * 32 + q]);
        *reinterpret_cast<uint4*>(&Bs[n * G1H_STRIDE + q * 4]) = v;
    }
    const uint4* A04 = reinterpret_cast<const uint4*>(A0h);
    const uint4* A14 = reinterpret_cast<const uint4*>(A1h);
    #pragma unroll
    for (int j = 0; j < 8; j++) {
        int i = tid + 256 * j;
        int r = i >> 4, q = i & 15;
        int row = m0 + r;
        uint4 v0 = make_uint4(0, 0, 0, 0), v1 = make_uint4(0, 0, 0, 0);
        if (row < M) {
            v0 = __ldg(&A04[(size_t)row * 16 + q]);
            v1 = __ldg(&A14[(size_t)row * 16 + q]);
        }
        *reinterpret_cast<uint4*>(&As[r * G1H_STRIDE + q * 4]) = v0;
        *reinterpret_cast<uint4*>(&As[r * G1H_STRIDE + 64 + q * 4]) = v1;
    }
    __syncthreads();

    float acc[2][8][4];
    #pragma unroll
    for (int mi = 0; mi < 2; mi++)
        #pragma unroll
        for (int ni = 0; ni < 8; ni++)
            #pragma unroll
            for (int q = 0; q < 4; q++) acc[mi][ni][q] = 0.f;

    #pragma unroll 4
    for (int kw = 0; kw < 16; kw++) {
        int kb = kw * 8;
        uint32_t afr[2][4];
        #pragma unroll
        for (int mi = 0; mi < 2; mi++) {
            int r = warpM * 32 + mi * 16 + g;
            afr[mi][0] = As[r * G1H_STRIDE + kb + tig];
            afr[mi][1] = As[(r + 8) * G1H_STRIDE + kb + tig];
            afr[mi][2] = As[r * G1H_STRIDE + kb + tig + 4];
            afr[mi][3] = As[(r + 8) * G1H_STRIDE + kb + tig + 4];
        }
        uint32_t bfr[8][2];
        #pragma unroll
        for (int ni = 0; ni < 8; ni++) {
            int n = warpN * 64 + ni * 8 + g;
            bfr[ni][0] = Bs[n * G1H_STRIDE + kb + tig];
            bfr[ni][1] = Bs[n * G1H_STRIDE + kb + tig + 4];
        }
        #pragma unroll
        for (int mi = 0; mi < 2; mi++)
            #pragma unroll
            for (int ni = 0; ni < 8; ni++)
                mma_f16(acc[mi][ni], afr[mi], bfr[ni]);
    }

    #pragma unroll
    for (int ni = 0; ni < 8; ni++) {
        int col = warpN * 64 + ni * 8 + tig * 2;
        float b0 = bias[col], b1 = bias[col + 1];
        float s0 = 0.f, q0 = 0.f, s1 = 0.f, q1 = 0.f;
        #pragma unroll
        for (int mi = 0; mi < 2; mi++) {
            int r0 = m0 + warpM * 32 + mi * 16 + g;
            if (r0 < M) {
                float v0 = acc[mi][ni][0] + b0;
                float v1 = acc[mi][ni][1] + b1;
                *reinterpret_cast<float2*>(&C[(size_t)r0 * 128 + col]) = make_float2(v0, v1);
                __half2 hh = __floats2half2_rn(v0, v1);
                *reinterpret_cast<uint32_t*>(&g_h16[(size_t)r0 * 128 + col]) =
                    *reinterpret_cast<uint32_t*>(&hh);
                s0 += v0; q0 += v0 * v0; s1 += v1; q1 += v1 * v1;
            }
            int r1 = r0 + 8;
            if (r1 < M) {
                float v2 = acc[mi][ni][2] + b0;
                float v3 = acc[mi][ni][3] + b1;
                *reinterpret_cast<float2*>(&C[(size_t)r1 * 128 + col]) = make_float2(v2, v3);
                __half2 hh = __floats2half2_rn(v2, v3);
                *reinterpret_cast<uint32_t*>(&g_h16[(size_t)r1 * 128 + col]) =
                    *reinterpret_cast<uint32_t*>(&hh);
                s0 += v2; q0 += v2 * v2; s1 += v3; q1 += v3 * v3;
            }
        }
        atomicAdd(&ssum[col], s0); atomicAdd(&ssq[col], q0);
        atomicAdd(&ssum[col + 1], s1); atomicAdd(&ssq[col + 1], q1);
    }
    __syncthreads();
    if (tid < 128) {
        atomicAdd(&g_colsum[tid], ssum[tid]);
        atomicAdd(&g_colsumsq[tid], ssq[tid]);
    }
}

// ---------------- layer-2 GEMM via mma.sync tf32 (N=32), frozen ----------------
#define G2_BSTRIDE 260
#define G2_ASTRIDE 68
#define G2_SMEM_BYTES ((32 * G2_BSTRIDE + 128 * G2_ASTRIDE + 256) * 4)

__global__ __launch_bounds__(256)
void gemm2_mma_kernel(const float* __restrict__ A0, const float* __restrict__ A1,
                      const float* __restrict__ Bt, const float* __restrict__ bias,
                      const float* __restrict__ gamma, const float* __restrict__ beta,
                      float invM, float* __restrict__ C, int M) {
    extern __shared__ float sm[];
    float* Bs   = sm;                      // [32][260]
    float* As   = sm + 32 * G2_BSTRIDE;    // [128][68]
    float* s_sc = As + 128 * G2_ASTRIDE;   // [128]
    float* s_sh = s_sc + 128;              // [128]

    int tid = threadIdx.x;
    int lane = tid & 31;
    int wid = tid >> 5;
    int g = lane >> 2;
    int tig = lane & 3;
    int m0 = blockIdx.x * 128;

    if (tid < 128) {
        float mean = g_colsum[tid] * invM;
        float var = g_colsumsq[tid] * invM - mean * mean;
        float sc = gamma[tid] * rsqrtf(var + 1e-5f);
        s_sc[tid] = sc;
        s_sh[tid] = beta[tid] - mean * sc;
    }

    const float4* Bt4 = reinterpret_cast<const float4*>(Bt);
    #pragma unroll
    for (int idx = tid; idx < 32 * 64; idx += 256) {
        int n = idx >> 6, k4 = idx & 63;
        float4 v = __ldg(&Bt4[n * 64 + k4]);
        *reinterpret_cast<float4*>(&Bs[n * G2_BSTRIDE + k4 * 4]) = v;
    }

    float acc[4][4];
    #pragma unroll
    for (int ni = 0; ni < 4; ni++)
        #pragma unroll
        for (int q = 0; q < 4; q++) acc[ni][q] = 0.f;

    float4 stage[8];
    {
        const float4* S4 = reinterpret_cast<const float4*>(A0);
        #pragma unroll
        for (int j = 0; j < 8; j++) {
            int i = tid + 256 * j;
            int r = i >> 4, c4 = i & 15;
            int row = m0 + r;
            stage[j] = (row < M) ? __ldg(&S4[(size_t)row * 32 + c4])
                                 : make_float4(0.f, 0.f, 0.f, 0.f);
        }
    }

    #pragma unroll 1
    for (int kc = 0; kc < 4; kc++) {
        __syncthreads();
        #pragma unroll
        for (int j = 0; j < 8; j++) {
            int i = tid + 256 * j;
            int r = i >> 4, c4 = i & 15;
            float4 v = stage[j];
            if (kc >= 2) {
                int cb = (kc & 1) * 64 + c4 * 4;
                v.x = fmaxf(fmaf(v.x, s_sc[cb + 0], s_sh[cb + 0]), 0.f);
                v.y = fmaxf(fmaf(v.y, s_sc[cb + 1], s_sh[cb + 1]), 0.f);
                v.z = fmaxf(fmaf(v.z, s_sc[cb + 2], s_sh[cb + 2]), 0.f);
                v.w = fmaxf(fmaf(v.w, s_sc[cb + 3], s_sh[cb + 3]), 0.f);
                v.x = f2tf32(v.x); v.y = f2tf32(v.y); v.z = f2tf32(v.z); v.w = f2tf32(v.w);
            }
            *reinterpret_cast<float4*>(&As[r * G2_ASTRIDE + c4 * 4]) = v;
        }
        if (kc < 3) {
            int nc = kc + 1;
            const float4* S4 = reinterpret_cast<const float4*>(nc < 2 ? A0 : A1);
            int cbase = (nc & 1) * 16;
            #pragma unroll
            for (int j = 0; j < 8; j++) {
                int i = tid + 256 * j;
                int r = i >> 4, c4 = i & 15;
                int row = m0 + r;
                stage[j] = (row < M) ? __ldg(&S4[(size_t)row * 32 + cbase + c4])
                                     : make_float4(0.f, 0.f, 0.f, 0.f);
            }
        }
        __syncthreads();

        const float* Bkc = Bs + kc * 64;
        #pragma unroll
        for (int ks = 0; ks < 8; ks++) {
            int k = ks * 8;
            uint32_t afr[4];
            int r = wid * 16 + g;
            afr[0] = __float_as_uint(As[r * G2_ASTRIDE + k + tig]);
            afr[1] = __float_as_uint(As[(r + 8) * G2_ASTRIDE + k + tig]);
            afr[2] = __float_as_uint(As[r * G2_ASTRIDE + k + tig + 4]);
            afr[3] = __float_as_uint(As[(r + 8) * G2_ASTRIDE + k + tig + 4]);
            uint32_t bfr[4][2];
            #pragma unroll
            for (int ni = 0; ni < 4; ni++) {
                int n = ni * 8 + g;
                bfr[ni][0] = __float_as_uint(Bkc[n * G2_BSTRIDE + k + tig]);
                bfr[ni][1] = __float_as_uint(Bkc[n * G2_BSTRIDE + k + tig + 4]);
            }
            #pragma unroll
            for (int ni = 0; ni < 4; ni++)
                mma_tf32(acc[ni], afr, bfr[ni]);
        }
    }

    #pragma unroll
    for (int ni = 0; ni < 4; ni++) {
        int col = ni * 8 + tig * 2;
        float b0 = bias[col], b1 = bias[col + 1];
        int r0 = m0 + wid * 16 + g;
        if (r0 < M)
            *reinterpret_cast<float2*>(&C[(size_t)r0 * 32 + col]) =
                make_float2(acc[ni][0] + b0, acc[ni][1] + b1);
        int r1 = r0 + 8;
        if (r1 < M)
            *reinterpret_cast<float2*>(&C[(size_t)r1 * 32 + col]) =
                make_float2(acc[ni][2] + b0, acc[ni][3] + b1);
    }
}

// ---------------- launch ----------------
extern "C" void kernel_launch(void* const* d_in, const int* in_sizes, int n_in,
                              void* d_out, int out_size) {
    const float* x     = (const float*)d_in[0];
    const int*   ei    = (const int*)d_in[1];
    const float* Wl1   = (const float*)d_in[2];
    const float* bl1   = (const float*)d_in[3];
    const float* Wr1   = (const float*)d_in[4];
    const float* gamma = (const float*)d_in[5];
    const float* beta  = (const float*)d_in[6];
    const float* Wl2   = (const float*)d_in[7];
    const float* bl2   = (const float*)d_in[8];
    const float* Wr2   = (const float*)d_in[9];
    float* out = (float*)d_out;

    int M = in_sizes[0] / D_IN;       // 50000
    int E = in_sizes[1] / 2;          // 800000
    const int* src = ei;
    const int* dst = ei + E;
    float invM = 1.0f / (float)M;

    float *p_agg, *p_h, *p_B2t;
    __half *p_x16, *p_h16, *p_agg16, *p_B1h;
    cudaGetSymbolAddress((void**)&p_agg,   g_agg);
    cudaGetSymbolAddress((void**)&p_h,     g_h);
    cudaGetSymbolAddress((void**)&p_B2t,   g_B2t);
    cudaGetSymbolAddress((void**)&p_x16,   g_x16);
    cudaGetSymbolAddress((void**)&p_h16,   g_h16);
    cudaGetSymbolAddress((void**)&p_agg16, g_agg16);
    cudaGetSymbolAddress((void**)&p_B1h,   g_B1h);

    cudaFuncSetAttribute(gemm1_f16_kernel,
                         cudaFuncAttributeMaxDynamicSharedMemorySize, G1H_SMEM_BYTES);
    cudaFuncSetAttribute(gemm2_mma_kernel,
                         cudaFuncAttributeMaxDynamicSharedMemorySize, G2_SMEM_BYTES);

    // CSR build + setup
    {
        int T = (E + 1) / 2;
        hist_kernel<<<(T + 255) / 256, 256>>>(dst, E, x, M * 32, T, Wl1, Wr1, Wl2, Wr2);
    }
    scan_kernel<<<(M + 255) / 256, 256>>>(M);
    scatter_kernel<<<((E + 1) / 2 + 255) / 256, 256>>>(src, dst, E);

    // layer 1: agg16 = scatter_max(x16) [exact fp16]; h = [agg16|x16] @ B1h + b1 (fp16 mma)
    agg16h_kernel<false><<<(M * 64 + 255) / 256, 256>>>(
        p_x16, nullptr, p_agg16, M, gamma, beta, invM);
    gemm1_f16_kernel<<<(M + 127) / 128, 256, G1H_SMEM_BYTES>>>(
        p_agg16, p_x16, p_B1h, bl1, p_h, M);

    // layer 2: agg2 = scatter_max(relu(bn(h16))) via hmax/hmin + hoisted transform
    agg16h_kernel<true><<<(M * 64 + 255) / 256, 256>>>(
        p_h16, p_agg, nullptr, M, gamma, beta, invM);
    gemm2_mma_kernel<<<(M + 127) / 128, 256, G2_SMEM_BYTES>>>(
        p_agg, p_h, p_B2t, bl2, gamma, beta, invM, out, M);
}

// round 17
// speedup vs baseline: 1.2746x; 1.2746x over previous
#include <cuda_runtime.h>
#include <cuda_bf16.h>
#include <cuda_fp16.h>
#include <math_constants.h>
#include <cstdint>

#define N_NODES 50000
#define N_EDGES 800000
#define D_IN 128
#define D_H 128
#define D_OUT 32

// ---------------- scratch (device globals; no allocation allowed) ----------------
__device__ int    g_cnt[N_NODES];          // zero-initialized at module load; scan re-zeroes
__device__ int    g_row_ptr[N_NODES + 1];
__device__ int    g_rank[N_EDGES];
__device__ int    g_col[N_EDGES];
__device__ float  g_agg[(size_t)N_NODES * D_H];    // fp32 agg (layer 2)
__device__ __half g_agg16[(size_t)N_NODES * D_H];  // fp16 agg (layer 1)
__device__ float  g_h[(size_t)N_NODES * D_H];
__device__ __half g_x16[(size_t)N_NODES * D_H];
__device__ __half g_h16[(size_t)N_NODES * D_H];
__device__ __half g_B1h[128 * 256];   // layer-1 weights [N=128][K=256] K-major, fp16
__device__ float  g_B2t[32 * 256];    // layer-2 weights [N=32][K=256]  K-major, tf32-rounded
__device__ float  g_colsum[D_H];
__device__ float  g_colsumsq[D_H];

__device__ __forceinline__ float f2tf32(float x) {
    float r;
    asm("cvt.rna.tf32.f32 %0, %1;" : "=f"(r) : "f"(x));
    return r;
}

// ---------------- CSR build + all setup in one kernel ----------------
__global__ void hist_kernel(const int* __restrict__ dst, int E,
                            const float* __restrict__ x, int total4, int T,
                            const float* __restrict__ Wl1, const float* __restrict__ Wr1,
                            const float* __restrict__ Wl2, const float* __restrict__ Wr2) {
    int t = blockIdx.x * blockDim.x + threadIdx.x;
    int e0 = t * 2;
    if (e0 < E) {
        int d0 = __ldg(&dst[e0]);
        if (e0 + 1 < E) {
            int d1 = __ldg(&dst[e0 + 1]);
            g_rank[e0] = atomicAdd(&g_cnt[d0], 1);
            g_rank[e0 + 1] = atomicAdd(&g_cnt[d1], 1);
        } else {
            g_rank[e0] = atomicAdd(&g_cnt[d0], 1);
        }
    }
    if (t < 128 * 256) {
        int n = t >> 8, k = t & 255;
        float v = (k < 128) ? __ldg(&Wl1[n * 128 + k]) : __ldg(&Wr1[n * 128 + (k - 128)]);
        g_B1h[t] = __float2half_rn(v);
    }
    if (t < 32 * 256) {
        int n = t >> 8, k = t & 255;
        float v = (k < 128) ? __ldg(&Wl2[n * 128 + k]) : __ldg(&Wr2[n * 128 + (k - 128)]);
        g_B2t[t] = f2tf32(v);
    }
    if (t < 128) { g_colsum[t] = 0.f; g_colsumsq[t] = 0.f; }
    const float4* X4 = reinterpret_cast<const float4*>(x);
    for (int idx = t; idx < total4; idx += T) {
        float4 v = __ldg(&X4[idx]);
        __half2 a = __floats2half2_rn(v.x, v.y);
        __half2 b = __floats2half2_rn(v.z, v.w);
        uint2 o;
        o.x = *reinterpret_cast<uint32_t*>(&a);
        o.y = *reinterpret_cast<uint32_t*>(&b);
        *reinterpret_cast<uint2*>(&g_x16[(size_t)idx * 4]) = o;
    }
}

// ---------------- triangular parallel exclusive scan (coalesced, multi-block) ----------
__global__ __launch_bounds__(256)
void scan_kernel(int n) {
    __shared__ int red[256];
    int tid = threadIdx.x;
    int base = blockIdx.x * 256;

    int sum = 0;
    for (int i = tid; i < base; i += 256) sum += g_cnt[i];
    red[tid] = sum;
    __syncthreads();
    #pragma unroll
    for (int d = 128; d > 0; d >>= 1) {
        if (tid < d) red[tid] += red[tid + d];
        __syncthreads();
    }
    int blockOff = red[0];
    __syncthreads();

    int i = base + tid;
    int v = (i < n) ? g_cnt[i] : 0;
    red[tid] = v;
    __syncthreads();
    #pragma unroll
    for (int d = 1; d < 256; d <<= 1) {
        int u = (tid >= d) ? red[tid - d] : 0;
        __syncthreads();
        red[tid] += u;
        __syncthreads();
    }
    int incl = red[tid];
    if (i < n) {
        g_row_ptr[i] = blockOff + incl - v;  // exclusive prefix
        g_cnt[i] = 0;                        // restore invariant for next call
        if (i == n - 1) g_row_ptr[n] = blockOff + incl;
    }
}

// atomic-free scatter, 2 edges/thread
__global__ void scatter_kernel(const int* __restrict__ src, const int* __restrict__ dst, int E) {
    int t = blockIdx.x * blockDim.x + threadIdx.x;
    int e0 = t * 2;
    if (e0 + 1 < E) {
        int d0 = __ldg(&dst[e0]),      d1 = __ldg(&dst[e0 + 1]);
        int r0 = __ldg(&g_rank[e0]),   r1 = __ldg(&g_rank[e0 + 1]);
        int s0 = __ldg(&src[e0]),      s1 = __ldg(&src[e0 + 1]);
        int p0 = __ldg(&g_row_ptr[d0]), p1 = __ldg(&g_row_ptr[d1]);
        g_col[p0 + r0] = s0;
        g_col[p1 + r1] = s1;
    } else if (e0 < E) {
        int d0 = __ldg(&dst[e0]);
        g_col[__ldg(&g_row_ptr[d0]) + __ldg(&g_rank[e0])] = __ldg(&src[e0]);
    }
}

// ---------------- scatter-max aggregation (R15 version: warp/node, MLP-4, int4 idx) --------
template <bool XFORM>
__global__ void agg16h_kernel(const __half* __restrict__ X16,
                              float* __restrict__ AGGF, __half* __restrict__ AGGH, int nNodes,
                              const float* __restrict__ gamma, const float* __restrict__ beta,
                              float invM) {
    __shared__ float s_sc[XFORM ? 128 : 1];
    __shared__ float s_sh[XFORM ? 128 : 1];
    int tid = threadIdx.x;
    if (XFORM) {
        if (tid < 128) {
            float mean = g_colsum[tid] * invM;
            float var = g_colsumsq[tid] * invM - mean * mean;
            float sc = gamma[tid] * rsqrtf(var + 1e-5f);
            s_sc[tid] = sc;
            s_sh[tid] = beta[tid] - mean * sc;
        }
        __syncthreads();
    }
    int warp = (blockIdx.x * blockDim.x + tid) >> 5;
    int lane = tid & 31;
    if (warp >= nNodes) return;
    int s = g_row_ptr[warp];
    int e = g_row_ptr[warp + 1];
    const uint2* X2 = reinterpret_cast<const uint2*>(X16);

    const uint32_t NEGI = 0xFC00FC00u;  // (-inf, -inf)
    const uint32_t POSI = 0x7C007C00u;  // (+inf, +inf)
    __half2 mx0 = *reinterpret_cast<const __half2*>(&NEGI);
    __half2 mx1 = mx0;
    __half2 mn0 = *reinterpret_cast<const __half2*>(&POSI);
    __half2 mn1 = mn0;

    int i = s;
    while (i < e && (i & 3)) {
        uint32_t c = (uint32_t)__ldg(&g_col[i]);
        uint2 p = __ldg(&X2[c * 32u + lane]);
        __half2 a0 = *reinterpret_cast<const __half2*>(&p.x);
        __half2 a1 = *reinterpret_cast<const __half2*>(&p.y);
        mx0 = __hmax2(mx0, a0); mx1 = __hmax2(mx1, a1);
        if (XFORM) { mn0 = __hmin2(mn0, a0); mn1 = __hmin2(mn1, a1); }
        i++;
    }
    #pragma unroll 2
    for (; i + 4 <= e; i += 4) {
        int4 c = *reinterpret_cast<const int4*>(&g_col[i]);  // one 16B uniform load
        uint2 p0 = __ldg(&X2[(uint32_t)c.x * 32u + lane]);
        uint2 p1 = __ldg(&X2[(uint32_t)c.y * 32u + lane]);
        uint2 p2 = __ldg(&X2[(uint32_t)c.z * 32u + lane]);
        uint2 p3 = __ldg(&X2[(uint32_t)c.w * 32u + lane]);
        __half2 a0 = *reinterpret_cast<const __half2*>(&p0.x);
        __half2 a1 = *reinterpret_cast<const __half2*>(&p0.y);
        __half2 b0 = *reinterpret_cast<const __half2*>(&p1.x);
        __half2 b1 = *reinterpret_cast<const __half2*>(&p1.y);
        __half2 d0 = *reinterpret_cast<const __half2*>(&p2.x);
        __half2 d1 = *reinterpret_cast<const __half2*>(&p2.y);
        __half2 e0 = *reinterpret_cast<const __half2*>(&p3.x);
        __half2 e1 = *reinterpret_cast<const __half2*>(&p3.y);
        mx0 = __hmax2(mx0, __hmax2(a0, b0));
        mx1 = __hmax2(mx1, __hmax2(a1, b1));
        mx0 = __hmax2(mx0, __hmax2(d0, e0));
        mx1 = __hmax2(mx1, __hmax2(d1, e1));
        if (XFORM) {
            mn0 = __hmin2(mn0, __hmin2(a0, b0));
            mn1 = __hmin2(mn1, __hmin2(a1, b1));
            mn0 = __hmin2(mn0, __hmin2(d0, e0));
            mn1 = __hmin2(mn1, __hmin2(d1, e1));
        }
    }
    for (; i < e; i++) {
        uint32_t c = (uint32_t)__ldg(&g_col[i]);
        uint2 p = __ldg(&X2[c * 32u + lane]);
        __half2 a0 = *reinterpret_cast<const __half2*>(&p.x);
        __half2 a1 = *reinterpret_cast<const __half2*>(&p.y);
        mx0 = __hmax2(mx0, a0); mx1 = __hmax2(mx1, a1);
        if (XFORM) { mn0 = __hmin2(mn0, a0); mn1 = __hmin2(mn1, a1); }
    }

    if (!XFORM) {
        uint2 o;
        if (s == e) { o.x = 0u; o.y = 0u; }
        else {
            o.x = *reinterpret_cast<uint32_t*>(&mx0);
            o.y = *reinterpret_cast<uint32_t*>(&mx1);
        }
        *reinterpret_cast<uint2*>(&AGGH[((size_t)warp << 7) + lane * 4]) = o;
    } else {
        float4 sc = *reinterpret_cast<const float4*>(&s_sc[lane * 4]);
        float4 sh = *reinterpret_cast<const float4*>(&s_sh[lane * 4]);
        float2 fx0 = __half22float2(mx0), fx1 = __half22float2(mx1);
        float2 fn0 = __half22float2(mn0), fn1 = __half22float2(mn1);
        float4 r;
        r.x = fmaxf(fmaf(sc.x >= 0.f ? fx0.x : fn0.x, sc.x, sh.x), 0.f);
        r.y = fmaxf(fmaf(sc.y >= 0.f ? fx0.y : fn0.y, sc.y, sh.y), 0.f);
        r.z = fmaxf(fmaf(sc.z >= 0.f ? fx1.x : fn1.x, sc.z, sh.z), 0.f);
        r.w = fmaxf(fmaf(sc.w >= 0.f ? fx1.y : fn1.y, sc.w, sh.w), 0.f);
        if (s == e) r = make_float4(0.f, 0.f, 0.f, 0.f);
        r.x = f2tf32(r.x); r.y = f2tf32(r.y); r.z = f2tf32(r.z); r.w = f2tf32(r.w);
        reinterpret_cast<float4*>(AGGF)[(size_t)warp * 32 + lane] = r;
    }
}

// ---------------- mma helpers ----------------
__device__ __forceinline__ void mma_f16(float* d, const uint32_t* a, const uint32_t* b) {
    asm volatile(
        "mma.sync.aligned.m16n8k16.row.col.f32.f16.f16.f32 "
        "{%0,%1,%2,%3}, {%4,%5,%6,%7}, {%8,%9}, {%0,%1,%2,%3};"
        : "+f"(d[0]), "+f"(d[1]), "+f"(d[2]), "+f"(d[3])
        : "r"(a[0]), "r"(a[1]), "r"(a[2]), "r"(a[3]), "r"(b[0]), "r"(b[1]));
}
__device__ __forceinline__ void mma_tf32(float* d, const uint32_t* a, const uint32_t* b) {
    asm volatile(
        "mma.sync.aligned.m16n8k8.row.col.f32.tf32.tf32.f32 "
        "{%0,%1,%2,%3}, {%4,%5,%6,%7}, {%8,%9}, {%0,%1,%2,%3};"
        : "+f"(d[0]), "+f"(d[1]), "+f"(d[2]), "+f"(d[3])
        : "r"(a[0]), "r"(a[1]), "r"(a[2]), "r"(a[3]), "r"(b[0]), "r"(b[1]));
}

// ---------------- layer-1 GEMM fp16 m16n8k16, N-split: grid.y picks 64-col half --------
// smem ~102KB -> 2 CTAs/SM (16 warps) for latency hiding. A duplicated across halves.
#define G1H_STRIDE 132
#define G1H_SMEM_WORDS (64 * G1H_STRIDE + 128 * G1H_STRIDE + 128)
#define G1H_SMEM_BYTES (G1H_SMEM_WORDS * 4)

__global__ __launch_bounds__(256, 2)
void gemm1_f16_kernel(const __half* __restrict__ A0h, const __half* __restrict__ A1h,
                      const __half* __restrict__ Bh, const float* __restrict__ bias,
                      float* __restrict__ C, int M) {
    extern __shared__ uint32_t smh[];
    uint32_t* Bs = smh;                                  // [64][132] half2 units (this N-half)
    uint32_t* As = smh + 64 * G1H_STRIDE;                // [128][132]
    float* ssum = reinterpret_cast<float*>(smh + 64 * G1H_STRIDE + 128 * G1H_STRIDE);
    float* ssq  = ssum + 64;

    int tid = threadIdx.x;
    int lane = tid & 31;
    int wid = tid >> 5;
    int warpM = wid & 3;      // 0..3 -> 32-row slabs
    int warpN = wid >> 2;     // 0..1 -> 32-col slabs within this 64-col half
    int g = lane >> 2;
    int tig = lane & 3;
    int m0 = blockIdx.x * 128;
    int n0 = blockIdx.y * 64;  // which B half

    if (tid < 64) { ssum[tid] = 0.f; ssq[tid] = 0.f; }

    // B half: 64 rows x 256 halves = 32 uint4/row -> 2048 uint4
    const uint4* B4 = reinterpret_cast<const uint4*>(Bh);
    #pragma unroll
    for (int j = 0; j < 8; j++) {
        int i = tid + 256 * j;
        int n = i >> 5, q = i & 31;
        uint4 v = __ldg(&B4[(n0 + n) * 32 + q]);
        *reinterpret_cast<uint4*>(&Bs[n * G1H_STRIDE + q * 4]) = v;
    }
    // A: full 128 rows x 256 halves
    const uint4* A04 = reinterpret_cast<const uint4*>(A0h);
    const uint4* A14 = reinterpret_cast<const uint4*>(A1h);
    #pragma unroll
    for (int j = 0; j < 8; j++) {
        int i = tid + 256 * j;
        int r = i >> 4, q = i & 15;
        int row = m0 + r;
        uint4 v0 = make_uint4(0, 0, 0, 0), v1 = make_uint4(0, 0, 0, 0);
        if (row < M) {
            v0 = __ldg(&A04[(size_t)row * 16 + q]);
            v1 = __ldg(&A14[(size_t)row * 16 + q]);
        }
        *reinterpret_cast<uint4*>(&As[r * G1H_STRIDE + q * 4]) = v0;
        *reinterpret_cast<uint4*>(&As[r * G1H_STRIDE + 64 + q * 4]) = v1;
    }
    __syncthreads();

    float acc[2][4][4];
    #pragma unroll
    for (int mi = 0; mi < 2; mi++)
        #pragma unroll
        for (int ni = 0; ni < 4; ni++)
            #pragma unroll
            for (int q = 0; q < 4; q++) acc[mi][ni][q] = 0.f;

    #pragma unroll 4
    for (int kw = 0; kw < 16; kw++) {
        int kb = kw * 8;
        uint32_t afr[2][4];
        #pragma unroll
        for (int mi = 0; mi < 2; mi++) {
            int r = warpM * 32 + mi * 16 + g;
            afr[mi][0] = As[r * G1H_STRIDE + kb + tig];
            afr[mi][1] = As[(r + 8) * G1H_STRIDE + kb + tig];
            afr[mi][2] = As[r * G1H_STRIDE + kb + tig + 4];
            afr[mi][3] = As[(r + 8) * G1H_STRIDE + kb + tig + 4];
        }
        uint32_t bfr[4][2];
        #pragma unroll
        for (int ni = 0; ni < 4; ni++) {
            int n = warpN * 32 + ni * 8 + g;
            bfr[ni][0] = Bs[n * G1H_STRIDE + kb + tig];
            bfr[ni][1] = Bs[n * G1H_STRIDE + kb + tig + 4];
        }
        #pragma unroll
        for (int mi = 0; mi < 2; mi++)
            #pragma unroll
            for (int ni = 0; ni < 4; ni++)
                mma_f16(acc[mi][ni], afr[mi], bfr[ni]);
    }

    // epilogue: bias + store fp32 & fp16 + fused BN column stats (this 64-col half)
    #pragma unroll
    for (int ni = 0; ni < 4; ni++) {
        int lcol = warpN * 32 + ni * 8 + tig * 2;  // local col in [0,64)
        int col = n0 + lcol;
        float b0 = bias[col], b1 = bias[col + 1];
        float s0 = 0.f, q0 = 0.f, s1 = 0.f, q1 = 0.f;
        #pragma unroll
        for (int mi = 0; mi < 2; mi++) {
            int r0 = m0 + warpM * 32 + mi * 16 + g;
            if (r0 < M) {
                float v0 = acc[mi][ni][0] + b0;
                float v1 = acc[mi][ni][1] + b1;
                *reinterpret_cast<float2*>(&C[(size_t)r0 * 128 + col]) = make_float2(v0, v1);
                __half2 hh = __floats2half2_rn(v0, v1);
                *reinterpret_cast<uint32_t*>(&g_h16[(size_t)r0 * 128 + col]) =
                    *reinterpret_cast<uint32_t*>(&hh);
                s0 += v0; q0 += v0 * v0; s1 += v1; q1 += v1 * v1;
            }
            int r1 = r0 + 8;
            if (r1 < M) {
                float v2 = acc[mi][ni][2] + b0;
                float v3 = acc[mi][ni][3] + b1;
                *reinterpret_cast<float2*>(&C[(size_t)r1 * 128 + col]) = make_float2(v2, v3);
                __half2 hh = __floats2half2_rn(v2, v3);
                *reinterpret_cast<uint32_t*>(&g_h16[(size_t)r1 * 128 + col]) =
                    *reinterpret_cast<uint32_t*>(&hh);
                s0 += v2; q0 += v2 * v2; s1 += v3; q1 += v3 * v3;
            }
        }
        atomicAdd(&ssum[lcol], s0); atomicAdd(&ssq[lcol], q0);
        atomicAdd(&ssum[lcol + 1], s1); atomicAdd(&ssq[lcol + 1], q1);
    }
    __syncthreads();
    if (tid < 64) {
        atomicAdd(&g_colsum[n0 + tid], ssum[tid]);
        atomicAdd(&g_colsumsq[n0 + tid], ssq[tid]);
    }
}

// ---------------- layer-2 GEMM via mma.sync tf32 (N=32), frozen ----------------
#define G2_BSTRIDE 260
#define G2_ASTRIDE 68
#define G2_SMEM_BYTES ((32 * G2_BSTRIDE + 128 * G2_ASTRIDE + 256) * 4)

__global__ __launch_bounds__(256)
void gemm2_mma_kernel(const float* __restrict__ A0, const float* __restrict__ A1,
                      const float* __restrict__ Bt, const float* __restrict__ bias,
                      const float* __restrict__ gamma, const float* __restrict__ beta,
                      float invM, float* __restrict__ C, int M) {
    extern __shared__ float sm[];
    float* Bs   = sm;                      // [32][260]
    float* As   = sm + 32 * G2_BSTRIDE;    // [128][68]
    float* s_sc = As + 128 * G2_ASTRIDE;   // [128]
    float* s_sh = s_sc + 128;              // [128]

    int tid = threadIdx.x;
    int lane = tid & 31;
    int wid = tid >> 5;
    int g = lane >> 2;
    int tig = lane & 3;
    int m0 = blockIdx.x * 128;

    if (tid < 128) {
        float mean = g_colsum[tid] * invM;
        float var = g_colsumsq[tid] * invM - mean * mean;
        float sc = gamma[tid] * rsqrtf(var + 1e-5f);
        s_sc[tid] = sc;
        s_sh[tid] = beta[tid] - mean * sc;
    }

    const float4* Bt4 = reinterpret_cast<const float4*>(Bt);
    #pragma unroll
    for (int idx = tid; idx < 32 * 64; idx += 256) {
        int n = idx >> 6, k4 = idx & 63;
        float4 v = __ldg(&Bt4[n * 64 + k4]);
        *reinterpret_cast<float4*>(&Bs[n * G2_BSTRIDE + k4 * 4]) = v;
    }

    float acc[4][4];
    #pragma unroll
    for (int ni = 0; ni < 4; ni++)
        #pragma unroll
        for (int q = 0; q < 4; q++) acc[ni][q] = 0.f;

    float4 stage[8];
    {
        const float4* S4 = reinterpret_cast<const float4*>(A0);
        #pragma unroll
        for (int j = 0; j < 8; j++) {
            int i = tid + 256 * j;
            int r = i >> 4, c4 = i & 15;
            int row = m0 + r;
            stage[j] = (row < M) ? __ldg(&S4[(size_t)row * 32 + c4])
                                 : make_float4(0.f, 0.f, 0.f, 0.f);
        }
    }

    #pragma unroll 1
    for (int kc = 0; kc < 4; kc++) {
        __syncthreads();
        #pragma unroll
        for (int j = 0; j < 8; j++) {
            int i = tid + 256 * j;
            int r = i >> 4, c4 = i & 15;
            float4 v = stage[j];
            if (kc >= 2) {
                int cb = (kc & 1) * 64 + c4 * 4;
                v.x = fmaxf(fmaf(v.x, s_sc[cb + 0], s_sh[cb + 0]), 0.f);
                v.y = fmaxf(fmaf(v.y, s_sc[cb + 1], s_sh[cb + 1]), 0.f);
                v.z = fmaxf(fmaf(v.z, s_sc[cb + 2], s_sh[cb + 2]), 0.f);
                v.w = fmaxf(fmaf(v.w, s_sc[cb + 3], s_sh[cb + 3]), 0.f);
                v.x = f2tf32(v.x); v.y = f2tf32(v.y); v.z = f2tf32(v.z); v.w = f2tf32(v.w);
            }
            *reinterpret_cast<float4*>(&As[r * G2_ASTRIDE + c4 * 4]) = v;
        }
        if (kc < 3) {
            int nc = kc + 1;
            const float4* S4 = reinterpret_cast<const float4*>(nc < 2 ? A0 : A1);
            int cbase = (nc & 1) * 16;
            #pragma unroll
            for (int j = 0; j < 8; j++) {
                int i = tid + 256 * j;
                int r = i >> 4, c4 = i & 15;
                int row = m0 + r;
                stage[j] = (row < M) ? __ldg(&S4[(size_t)row * 32 + cbase + c4])
                                     : make_float4(0.f, 0.f, 0.f, 0.f);
            }
        }
        __syncthreads();

        const float* Bkc = Bs + kc * 64;
        #pragma unroll
        for (int ks = 0; ks < 8; ks++) {
            int k = ks * 8;
            uint32_t afr[4];
            int r = wid * 16 + g;
            afr[0] = __float_as_uint(As[r * G2_ASTRIDE + k + tig]);
            afr[1] = __float_as_uint(As[(r + 8) * G2_ASTRIDE + k + tig]);
            afr[2] = __float_as_uint(As[r * G2_ASTRIDE + k + tig + 4]);
            afr[3] = __float_as_uint(As[(r + 8) * G2_ASTRIDE + k + tig + 4]);
            uint32_t bfr[4][2];
            #pragma unroll
            for (int ni = 0; ni < 4; ni++) {
                int n = ni * 8 + g;
                bfr[ni][0] = __float_as_uint(Bkc[n * G2_BSTRIDE + k + tig]);
                bfr[ni][1] = __float_as_uint(Bkc[n * G2_BSTRIDE + k + tig + 4]);
            }
            #pragma unroll
            for (int ni = 0; ni < 4; ni++)
                mma_tf32(acc[ni], afr, bfr[ni]);
        }
    }

    #pragma unroll
    for (int ni = 0; ni < 4; ni++) {
        int col = ni * 8 + tig * 2;
        float b0 = bias[col], b1 = bias[col + 1];
        int r0 = m0 + wid * 16 + g;
        if (r0 < M)
            *reinterpret_cast<float2*>(&C[(size_t)r0 * 32 + col]) =
                make_float2(acc[ni][0] + b0, acc[ni][1] + b1);
        int r1 = r0 + 8;
        if (r1 < M)
            *reinterpret_cast<float2*>(&C[(size_t)r1 * 32 + col]) =
                make_float2(acc[ni][2] + b0, acc[ni][3] + b1);
    }
}

// ---------------- launch ----------------
extern "C" void kernel_launch(void* const* d_in, const int* in_sizes, int n_in,
                              void* d_out, int out_size) {
    const float* x     = (const float*)d_in[0];
    const int*   ei    = (const int*)d_in[1];
    const float* Wl1   = (const float*)d_in[2];
    const float* bl1   = (const float*)d_in[3];
    const float* Wr1   = (const float*)d_in[4];
    const float* gamma = (const float*)d_in[5];
    const float* beta  = (const float*)d_in[6];
    const float* Wl2   = (const float*)d_in[7];
    const float* bl2   = (const float*)d_in[8];
    const float* Wr2   = (const float*)d_in[9];
    float* out = (float*)d_out;

    int M = in_sizes[0] / D_IN;       // 50000
    int E = in_sizes[1] / 2;          // 800000
    const int* src = ei;
    const int* dst = ei + E;
    float invM = 1.0f / (float)M;

    float *p_agg, *p_h, *p_B2t;
    __half *p_x16, *p_h16, *p_agg16, *p_B1h;
    cudaGetSymbolAddress((void**)&p_agg,   g_agg);
    cudaGetSymbolAddress((void**)&p_h,     g_h);
    cudaGetSymbolAddress((void**)&p_B2t,   g_B2t);
    cudaGetSymbolAddress((void**)&p_x16,   g_x16);
    cudaGetSymbolAddress((void**)&p_h16,   g_h16);
    cudaGetSymbolAddress((void**)&p_agg16, g_agg16);
    cudaGetSymbolAddress((void**)&p_B1h,   g_B1h);

    cudaFuncSetAttribute(gemm1_f16_kernel,
                         cudaFuncAttributeMaxDynamicSharedMemorySize, G1H_SMEM_BYTES);
    cudaFuncSetAttribute(gemm2_mma_kernel,
                         cudaFuncAttributeMaxDynamicSharedMemorySize, G2_SMEM_BYTES);

    // CSR build + setup
    {
        int T = (E + 1) / 2;
        hist_kernel<<<(T + 255) / 256, 256>>>(dst, E, x, M * 32, T, Wl1, Wr1, Wl2, Wr2);
    }
    scan_kernel<<<(M + 255) / 256, 256>>>(M);
    scatter_kernel<<<((E + 1) / 2 + 255) / 256, 256>>>(src, dst, E);

    // layer 1: agg16 = scatter_max(x16) [exact fp16]; h = [agg16|x16] @ B1h + b1 (fp16 mma)
    agg16h_kernel<false><<<(M * 32 + 255) / 256, 256>>>(
        p_x16, nullptr, p_agg16, M, gamma, beta, invM);
    {
        dim3 grid((M + 127) / 128, 2);
        gemm1_f16_kernel<<<grid, 256, G1H_SMEM_BYTES>>>(
            p_agg16, p_x16, p_B1h, bl1, p_h, M);
    }

    // layer 2: agg2 = scatter_max(relu(bn(h16))) via hmax/hmin + hoisted transform
    agg16h_kernel<true><<<(M * 32 + 255) / 256, 256>>>(
        p_h16, p_agg, nullptr, M, gamma, beta, invM);
    gemm2_mma_kernel<<<(M + 127) / 128, 256, G2_SMEM_BYTES>>>(
        p_agg, p_h, p_B2t, bl2, gamma, beta, invM, out, M);
}